// round 15
// baseline (speedup 1.0000x reference)
#include <cuda_runtime.h>
#include <cuda_fp16.h>
#include <cstdint>
#include <math.h>

#define VV 2048
#define LP1 33
#define SEQ_OFF   0
#define PROBS_OFF (512*33)
#define LOGP_OFF  (PROBS_OFF + 512*33*2048)
#define ENT_OFF   (LOGP_OFF + 512*33)

// fp16 x 3-product split, K' = 3*512 = 1536.
#define KP 1536

// ---------------------------------------------------------------------------
// Persistent device scratch
// ---------------------------------------------------------------------------
__device__ __half g_Whh[2048 * KP];
__device__ __half g_Wih[2048 * KP];
__device__ __half g_Wo [2048 * KP];
__device__ __half g_E6p[2176 * KP];
__device__ __half g_Ah [2][512 * KP];
__device__ float g_EG[2176 * 2048];
__device__ float g_z [2][512 * 2048];   // logits ping-pong (deferred probs)
__device__ float g_P [512 * 2048];
__device__ float g_gum[512 * 2048];
__device__ float g_mls[2][512];         // per-row M+lse, ping-pong
__device__ float g_bg[2048];
__device__ float g_c [512 * 512];

// ---------------------------------------------------------------------------
__device__ __forceinline__ uint32_t smem_to_u32(const void* p) {
  uint32_t a;
  asm("{ .reg .u64 t; cvta.to.shared.u64 t, %1; cvt.u32.u64 %0, t; }"
      : "=r"(a) : "l"(p));
  return a;
}

__device__ __forceinline__ void split3A(float f, __half* dst, int stride) {
  __half a0 = __float2half_rn(f);
  float a0f = __half2float(a0);
  __half a1 = __float2half_rn((f - a0f) * 64.0f);
  dst[0]          = a0;
  dst[stride]     = __float2half_rn(a0f * 0.03125f);
  dst[2 * stride] = a1;
}

__device__ __forceinline__ void split3B(float f, __half* dst, int stride) {
  __half b0 = __float2half_rn(f);
  float b0f = __half2float(b0);
  __half b1 = __float2half_rn((f - b0f) * 64.0f);
  float b1f = __half2float(b1);
  dst[0]          = b0;
  dst[stride]     = __float2half_rn(b1f * 0.5f);
  dst[2 * stride] = __float2half_rn(b0f * 0.015625f);
}

// Threefry2x32 (exact JAX constants) — device
__device__ __forceinline__ void tf2x32(uint32_t k0, uint32_t k1,
                                       uint32_t x0, uint32_t x1,
                                       uint32_t& o0, uint32_t& o1) {
  uint32_t ks2 = k0 ^ k1 ^ 0x1BD11BDAu;
#define TF_ROT(x,r) (((x) << (r)) | ((x) >> (32 - (r))))
#define TF_RND(r) { x0 += x1; x1 = TF_ROT(x1, r); x1 ^= x0; }
  x0 += k0; x1 += k1;
  TF_RND(13) TF_RND(15) TF_RND(26) TF_RND(6)   x0 += k1;  x1 += ks2 + 1u;
  TF_RND(17) TF_RND(29) TF_RND(16) TF_RND(24)  x0 += ks2; x1 += k0 + 2u;
  TF_RND(13) TF_RND(15) TF_RND(26) TF_RND(6)   x0 += k0;  x1 += k1 + 3u;
  TF_RND(17) TF_RND(29) TF_RND(16) TF_RND(24)  x0 += k1;  x1 += ks2 + 4u;
  TF_RND(13) TF_RND(15) TF_RND(26) TF_RND(6)   x0 += ks2; x1 += k0 + 5u;
  o0 = x0; o1 = x1;
#undef TF_RND
#undef TF_ROT
}

static void h_tf2x32(uint32_t k0, uint32_t k1, uint32_t x0, uint32_t x1,
                     uint32_t& o0, uint32_t& o1) {
  uint32_t ks2 = k0 ^ k1 ^ 0x1BD11BDAu;
#define TF_ROT(x,r) (((x) << (r)) | ((x) >> (32 - (r))))
#define TF_RND(r) { x0 += x1; x1 = TF_ROT(x1, r); x1 ^= x0; }
  x0 += k0; x1 += k1;
  TF_RND(13) TF_RND(15) TF_RND(26) TF_RND(6)   x0 += k1;  x1 += ks2 + 1u;
  TF_RND(17) TF_RND(29) TF_RND(16) TF_RND(24)  x0 += ks2; x1 += k0 + 2u;
  TF_RND(13) TF_RND(15) TF_RND(26) TF_RND(6)   x0 += k0;  x1 += k1 + 3u;
  TF_RND(17) TF_RND(29) TF_RND(16) TF_RND(24)  x0 += k1;  x1 += ks2 + 4u;
  TF_RND(13) TF_RND(15) TF_RND(26) TF_RND(6)   x0 += ks2; x1 += k0 + 5u;
  o0 = x0; o1 = x1;
#undef TF_RND
#undef TF_ROT
}

__device__ __forceinline__ float sigf(float x) { return 1.0f / (1.0f + expf(-x)); }

__device__ __forceinline__ int perm_orig(int pn) {
  int hg = pn >> 6, gate = (pn >> 4) & 3, hl = pn & 15;
  return gate * 512 + hg * 16 + hl;
}

__device__ __forceinline__ float gumbel_of(uint32_t sk0, uint32_t sk1, uint32_t idx) {
  uint32_t o0, o1;
  tf2x32(sk0, sk1, 0u, idx, o0, o1);
  uint32_t bits = o0 ^ o1;
  float f = __uint_as_float((bits >> 9) | 0x3f800000u) - 1.0f;
  float u = fmaxf(f, 1.1754943508222875e-38f);
  return -__logf(-__logf(u));
}

__device__ __forceinline__ float lstm_one(const float* __restrict__ P,
                                          const float* __restrict__ eg,
                                          int b, int hh) {
  int hg = hh >> 4, hl = hh & 15;
  int pn = hg * 64 + hl;
  float gi = P[pn]      + eg[pn]      + g_bg[pn];
  float gf = P[pn + 16] + eg[pn + 16] + g_bg[pn + 16];
  float gg = P[pn + 32] + eg[pn + 32] + g_bg[pn + 32];
  float go = P[pn + 48] + eg[pn + 48] + g_bg[pn + 48];
  int ci = b * 512 + hh;
  float cold = g_c[ci];
  float cn = sigf(gf) * cold + sigf(gi) * tanhf(gg);
  float hn = sigf(go) * tanhf(cn);
  g_c[ci] = cn;
  return hn;
}

// ---------------------------------------------------------------------------
// Setup kernels
// ---------------------------------------------------------------------------
__global__ __launch_bounds__(256) void k_split_wall(const float* __restrict__ whh,
                                                    const float* __restrict__ wih,
                                                    const float* __restrict__ ow) {
  __shared__ float t[32][33];
  const int bx = blockIdx.x, ky = blockIdx.y, which = blockIdx.z;
  const int tx = threadIdx.x & 31, ty = threadIdx.x >> 5;
  const float* w = (which == 0) ? whh : (which == 1) ? wih : ow;
  const int col = (which == 2) ? (bx * 32 + tx) : perm_orig(bx * 32 + tx);
#pragma unroll
  for (int r = 0; r < 4; r++) {
    int kl = ty + r * 8;
    t[kl][tx] = w[(size_t)(ky * 32 + kl) * 2048 + col];
  }
  __syncthreads();
  __half* G = (which == 0) ? g_Whh : (which == 1) ? g_Wih : g_Wo;
#pragma unroll
  for (int r = 0; r < 4; r++) {
    int nl = ty + r * 8;
    int pn = bx * 32 + nl;
    int k = ky * 32 + tx;
    split3B(t[tx][nl], &G[(size_t)pn * KP + k], 512);
  }
}

__global__ __launch_bounds__(256) void k_split_emb(const float* __restrict__ emb,
                                                   const float* __restrict__ sos) {
  int idx = blockIdx.x * 256 + threadIdx.x;       // 2176*512
  int v = idx >> 9, c = idx & 511;
  float f = (v < 2048) ? emb[idx] : (v == 2048 ? sos[c] : 0.0f);
  split3A(f, &g_E6p[(size_t)v * KP + c], 512);
}

__global__ __launch_bounds__(256) void k_init(const float* __restrict__ b_ih,
                                              const float* __restrict__ b_hh,
                                              float* __restrict__ out) {
  int idx = blockIdx.x * 256 + threadIdx.x;       // 512*2048
  int b = idx >> 11, v = idx & 2047;
  out[(size_t)PROBS_OFF + ((size_t)b * LP1 + 32) * VV + v] = 1.0f;
  if (v < 512) g_c[b * 512 + v] = 0.0f;
  if (b == 0) {
    int o = perm_orig(v);
    g_bg[v] = b_ih[o] + b_hh[o];
  }
  if (v == 0) {
    out[SEQ_OFF  + b * LP1 + 32] = 0.0f;
    out[LOGP_OFF + b * LP1 + 32] = 0.0f;
    out[ENT_OFF  + b * LP1 + 32] = 0.0f;
  }
}

// ---------------------------------------------------------------------------
// SIMT fp32 GEMM for h0 (once): h0 -> g_Ah[1]
// ---------------------------------------------------------------------------
__global__ __launch_bounds__(256) void k_h0(const float* __restrict__ A,
                                            const float* __restrict__ W,
                                            const float* __restrict__ bias) {
  const int N = 512, K = 1024;
  __shared__ float As[64][17];
  __shared__ float Ws[16][64];
  const int tid = threadIdx.x;
  const int tx = tid & 15, ty = tid >> 4;
  const int m0 = blockIdx.y * 64, n0 = blockIdx.x * 64;
  float acc[4][4];
#pragma unroll
  for (int r = 0; r < 4; r++)
#pragma unroll
    for (int c = 0; c < 4; c++) acc[r][c] = 0.f;
  for (int kb = 0; kb < K; kb += 16) {
#pragma unroll
    for (int i = 0; i < 4; i++) {
      int idx = tid + i * 256;
      As[idx >> 4][idx & 15] = A[(size_t)(m0 + (idx >> 4)) * K + kb + (idx & 15)];
    }
#pragma unroll
    for (int i = 0; i < 4; i++) {
      int idx = tid + i * 256;
      Ws[idx >> 6][idx & 63] = W[(size_t)(kb + (idx >> 6)) * N + n0 + (idx & 63)];
    }
    __syncthreads();
#pragma unroll
    for (int k = 0; k < 16; k++) {
      float a[4], w[4];
#pragma unroll
      for (int r = 0; r < 4; r++) a[r] = As[ty * 4 + r][k];
#pragma unroll
      for (int c = 0; c < 4; c++) w[c] = Ws[k][tx * 4 + c];
#pragma unroll
      for (int r = 0; r < 4; r++)
#pragma unroll
        for (int c = 0; c < 4; c++) acc[r][c] = fmaf(a[r], w[c], acc[r][c]);
    }
    __syncthreads();
  }
#pragma unroll
  for (int r = 0; r < 4; r++)
#pragma unroll
    for (int c = 0; c < 4; c++) {
      int row = m0 + ty * 4 + r, col = n0 + tx * 4 + c;
      float hn = acc[r][c] + bias[col];
      split3A(hn, &g_Ah[1][(size_t)row * KP + col], 512);
    }
}

// ---------------------------------------------------------------------------
// fp16 HMMA GEMM core: 128x128 CTA tile, warp tile 64x32, BK=32, 3-stage.
// ---------------------------------------------------------------------------
#define LDM_X4(r0,r1,r2,r3,addr) \
  asm volatile("ldmatrix.sync.aligned.m8n8.x4.shared.b16 {%0,%1,%2,%3}, [%4];" \
               : "=r"(r0), "=r"(r1), "=r"(r2), "=r"(r3) : "r"(addr))
#define MMA16816(c0,c1,c2,c3,a0,a1,a2,a3,b0,b1) \
  asm volatile("mma.sync.aligned.m16n8k16.row.col.f32.f16.f16.f32 " \
               "{%0,%1,%2,%3}, {%4,%5,%6,%7}, {%8,%9}, {%0,%1,%2,%3};" \
               : "+f"(c0), "+f"(c1), "+f"(c2), "+f"(c3) \
               : "r"(a0), "r"(a1), "r"(a2), "r"(a3), "r"(b0), "r"(b1))

#define STG_STRIDE 20480
#define SMEM_G (3 * STG_STRIDE)

__device__ __forceinline__ void gemm_core(const __half* __restrict__ A,
                                          const __half* __restrict__ Bt,
                                          int m0, int n0, float acc[4][4][4]) {
  constexpr int KT = KP / 32;      // 48
  extern __shared__ __half sm[];
  const uint32_t sbase = smem_to_u32(sm);
  const int tid = threadIdx.x;
  const int l = tid & 31, w = tid >> 5;
  const int wm = (w & 1) * 64, wn = (w >> 1) * 32;
  const int lr = tid >> 2, lc = (tid & 3) * 8;

#define LOAD_STAGE(st, kt) do {                                               \
    int kk_ = (kt) * 32;                                                      \
    uint32_t da_ = sbase + (st) * STG_STRIDE + (lr * 40 + lc) * 2;            \
    const __half* ga_ = A + (size_t)(m0 + lr) * KP + kk_ + lc;                \
    asm volatile("cp.async.cg.shared.global [%0], [%1], 16;"                  \
                 :: "r"(da_), "l"(ga_));                                      \
    asm volatile("cp.async.cg.shared.global [%0], [%1], 16;"                  \
                 :: "r"(da_ + 64 * 80), "l"(ga_ + (size_t)64 * KP));          \
    uint32_t db_ = da_ + 10240;                                               \
    const __half* gb_ = Bt + (size_t)(n0 + lr) * KP + kk_ + lc;               \
    asm volatile("cp.async.cg.shared.global [%0], [%1], 16;"                  \
                 :: "r"(db_), "l"(gb_));                                      \
    asm volatile("cp.async.cg.shared.global [%0], [%1], 16;"                  \
                 :: "r"(db_ + 64 * 80), "l"(gb_ + (size_t)64 * KP));          \
    asm volatile("cp.async.commit_group;");                                   \
  } while (0)

  LOAD_STAGE(0, 0);
  LOAD_STAGE(1, 1);

  for (int kt = 0; kt < KT; kt++) {
    if (kt + 1 < KT) asm volatile("cp.async.wait_group 1;");
    else             asm volatile("cp.async.wait_group 0;");
    __syncthreads();
    if (kt + 2 < KT) LOAD_STAGE((kt + 2) % 3, kt + 2);

    const uint32_t abase = sbase + (kt % 3) * STG_STRIDE;
    const uint32_t bbase = abase + 10240;
#pragma unroll
    for (int kk = 0; kk < 32; kk += 16) {
      uint32_t af[4][4];
#pragma unroll
      for (int fm = 0; fm < 4; fm++) {
        int row = wm + fm * 16 + (l & 15);
        int col = kk + (l >> 4) * 8;
        LDM_X4(af[fm][0], af[fm][1], af[fm][2], af[fm][3],
               abase + (row * 40 + col) * 2);
      }
      uint32_t bf[2][4];
#pragma unroll
      for (int f2 = 0; f2 < 2; f2++) {
        int row = wn + f2 * 16 + ((l >> 4) << 3) + (l & 7);
        int col = kk + ((l >> 3) & 1) * 8;
        LDM_X4(bf[f2][0], bf[f2][1], bf[f2][2], bf[f2][3],
               bbase + (row * 40 + col) * 2);
      }
#pragma unroll
      for (int fm = 0; fm < 4; fm++)
#pragma unroll
        for (int fn = 0; fn < 4; fn++) {
          uint32_t b0 = bf[fn >> 1][(fn & 1) * 2];
          uint32_t b1 = bf[fn >> 1][(fn & 1) * 2 + 1];
          MMA16816(acc[fm][fn][0], acc[fm][fn][1], acc[fm][fn][2], acc[fm][fn][3],
                   af[fm][0], af[fm][1], af[fm][2], af[fm][3], b0, b1);
        }
    }
  }
#undef LOAD_STAGE
}

__device__ __forceinline__ void store_tile(float* __restrict__ out, int m0, int n0,
                                           float acc[4][4][4],
                                           const float* __restrict__ bias) {
  const int l = threadIdx.x & 31, w = threadIdx.x >> 5;
  const int wm = (w & 1) * 64, wn = (w >> 1) * 32;
#pragma unroll
  for (int fm = 0; fm < 4; fm++)
#pragma unroll
    for (int fn = 0; fn < 4; fn++) {
      int r = m0 + wm + fm * 16 + (l >> 2);
      int c = n0 + wn + fn * 8 + (l & 3) * 2;
      float b0 = bias ? bias[c] : 0.f;
      float b1 = bias ? bias[c + 1] : 0.f;
      *(float2*)&out[(size_t)r * 2048 + c] =
          make_float2(acc[fm][fn][0] + b0, acc[fm][fn][1] + b1);
      *(float2*)&out[(size_t)(r + 8) * 2048 + c] =
          make_float2(acc[fm][fn][2] + b0, acc[fm][fn][3] + b1);
    }
}

// Merged step GEMM + service CTAs: grid (37, 4) = 148 CTAs.
// bx<16 -> z tiles; 16<=bx<32 -> P tiles; bx>=32 -> 20 service CTAs:
// gumbel hash for step t, then deferred probs/entropy flush for step pt.
__global__ __launch_bounds__(256) void k_mgemm(int ain, const float* __restrict__ ob,
                                               uint32_t sk0, uint32_t sk1,
                                               int zsel, int pt,
                                               float* __restrict__ out) {
  if (blockIdx.x >= 32) {
    const int id = (blockIdx.x - 32) * 4 + blockIdx.y;   // 0..19
    const int tid = threadIdx.x;
    int gid = id * 256 + tid;
    for (uint32_t idx = (uint32_t)gid; idx < 1048576u; idx += 5120u)
      g_gum[idx] = gumbel_of(sk0, sk1, idx);
    if (pt >= 0) {
      const float* __restrict__ zp = g_z[pt & 1];
      const int wid = id * 8 + (tid >> 5), lane = tid & 31;
      for (int b = wid; b < 512; b += 160) {
        float mls = g_mls[pt & 1][b];
        const float* __restrict__ zr = &zp[(size_t)b * 2048];
        size_t prow = (size_t)PROBS_OFF + ((size_t)b * LP1 + pt) * 2048;
        float ent = 0.f;
        for (int v = lane; v < 2048; v += 32) {
          float lsm = zr[v] - mls;
          float pr = __expf(lsm);
          out[prow + v] = pr;
          ent += pr * lsm;
        }
#pragma unroll
        for (int o = 16; o > 0; o >>= 1)
          ent += __shfl_down_sync(0xffffffffu, ent, o);
        if (lane == 0) out[ENT_OFF + b * LP1 + pt] = -ent;
      }
    }
    return;
  }
  const int half = blockIdx.x >> 4;
  const int m0 = blockIdx.y * 128, n0 = (blockIdx.x & 15) * 128;
  float acc[4][4][4];
#pragma unroll
  for (int a = 0; a < 4; a++)
#pragma unroll
    for (int b = 0; b < 4; b++)
#pragma unroll
      for (int c = 0; c < 4; c++) acc[a][b][c] = 0.f;
  gemm_core(g_Ah[ain], half ? g_Whh : g_Wo, m0, n0, acc);
  if (half) store_tile(g_P, m0, n0, acc, nullptr);
  else      store_tile(g_z[zsel], m0, n0, acc, ob);
}

// EG precompute: g_EG = E6p @ Wih, grid (16, 17)
__global__ __launch_bounds__(256) void k_eg() {
  const int m0 = blockIdx.y * 128, n0 = blockIdx.x * 128;
  float acc[4][4][4];
#pragma unroll
  for (int a = 0; a < 4; a++)
#pragma unroll
    for (int b = 0; b < 4; b++)
#pragma unroll
      for (int c = 0; c < 4; c++) acc[a][b][c] = 0.f;
  gemm_core(g_E6p, g_Wih, m0, n0, acc);
  store_tile(g_EG, m0, n0, acc, nullptr);
}

// ---------------------------------------------------------------------------
// LSTM0: iteration-0 LSTM (sym = sos row 2048) -> g_Ah[0].
// ---------------------------------------------------------------------------
__global__ __launch_bounds__(256) void k_lstm0() {
  const int b = blockIdx.x, tid = threadIdx.x;
  const float* __restrict__ P = &g_P[(size_t)b * 2048];
  const float* __restrict__ eg = &g_EG[(size_t)2048 * 2048];
#pragma unroll
  for (int r = 0; r < 2; r++) {
    int hh = tid + r * 256;
    float hn = lstm_one(P, eg, b, hh);
    split3A(hn, &g_Ah[0][(size_t)b * KP + hh], 512);
  }
}

// ---------------------------------------------------------------------------
// Crit sampler(t): max, lse, Gumbel-argmax, seq/logp, save M+lse, LSTM(t+1).
// Probs/entropy deferred to next mgemm's service CTAs.
// ---------------------------------------------------------------------------
__global__ __launch_bounds__(256) void k_sample(float* __restrict__ out, int t) {
  const int b = blockIdx.x;
  const int tid = threadIdx.x;
  const float* __restrict__ z   = &g_z[t & 1][(size_t)b * VV];
  const float* __restrict__ gum = &g_gum[(size_t)b * VV];

  float zv[8];
#pragma unroll
  for (int j = 0; j < 8; j++) zv[j] = z[tid + j * 256];

  __shared__ float red[256];
  __shared__ float rv[256];
  __shared__ int   ri[256];
  __shared__ int   s_sym;

  float m = zv[0];
#pragma unroll
  for (int j = 1; j < 8; j++) m = fmaxf(m, zv[j]);
  red[tid] = m; __syncthreads();
  for (int s = 128; s > 0; s >>= 1) {
    if (tid < s) red[tid] = fmaxf(red[tid], red[tid + s]);
    __syncthreads();
  }
  const float M = red[0]; __syncthreads();

  float ssum = 0.f;
#pragma unroll
  for (int j = 0; j < 8; j++) ssum += __expf(zv[j] - M);
  red[tid] = ssum; __syncthreads();
  for (int s = 128; s > 0; s >>= 1) {
    if (tid < s) red[tid] += red[tid + s];
    __syncthreads();
  }
  const float lse = logf(red[0]); __syncthreads();

  float bestv = -INFINITY;
  int   besti = VV;
#pragma unroll
  for (int j = 0; j < 8; j++) {
    int v = tid + j * 256;
    float lsm = zv[j] - M - lse;
    float val = gum[v] + lsm;
    if (val > bestv || (val == bestv && v < besti)) { bestv = val; besti = v; }
  }

  rv[tid] = bestv; ri[tid] = besti; __syncthreads();
  for (int s = 128; s > 0; s >>= 1) {
    if (tid < s) {
      if (rv[tid + s] > rv[tid] ||
          (rv[tid + s] == rv[tid] && ri[tid + s] < ri[tid])) {
        rv[tid] = rv[tid + s]; ri[tid] = ri[tid + s];
      }
    }
    __syncthreads();
  }
  if (tid == 0) {
    int sym = ri[0];
    s_sym = sym;
    out[SEQ_OFF  + b * LP1 + t] = (float)sym;
    out[LOGP_OFF + b * LP1 + t] = z[sym] - M - lse;
    g_mls[t & 1][b] = M + lse;
  }
  __syncthreads();
  const int sym = s_sym;

  // LSTM(t+1)
  const float* __restrict__ P  = &g_P[(size_t)b * 2048];
  const float* __restrict__ eg = &g_EG[(size_t)sym * 2048];
  __half* Aout = &g_Ah[(t + 1) & 1][(size_t)b * KP];
#pragma unroll
  for (int r = 0; r < 2; r++) {
    int hh = tid + r * 256;
    float hn = lstm_one(P, eg, b, hh);
    split3A(hn, &Aout[hh], 512);
  }
}

// Tail flush: probs/entropy for the last step (t=31).
__global__ __launch_bounds__(256) void k_ptail(float* __restrict__ out) {
  const int b = blockIdx.x, tid = threadIdx.x;
  const int pt = 31;
  const float* __restrict__ z = &g_z[pt & 1][(size_t)b * VV];
  const float mls = g_mls[pt & 1][b];
  __shared__ float red[256];
  float ent = 0.f;
  const size_t prow = (size_t)PROBS_OFF + ((size_t)b * LP1 + pt) * VV;
#pragma unroll
  for (int j = 0; j < 8; j++) {
    int v = tid + j * 256;
    float lsm = z[v] - mls;
    float pr = __expf(lsm);
    out[prow + v] = pr;
    ent += pr * lsm;
  }
  red[tid] = ent; __syncthreads();
  for (int s = 128; s > 0; s >>= 1) {
    if (tid < s) red[tid] += red[tid + s];
    __syncthreads();
  }
  if (tid == 0) out[ENT_OFF + b * LP1 + pt] = -red[0];
}

// ---------------------------------------------------------------------------
extern "C" void kernel_launch(void* const* d_in, const int* in_sizes, int n_in,
                              void* d_out, int out_size) {
  const float* x       = (const float*)d_in[0];
  const float* agent_w = (const float*)d_in[1];
  const float* agent_b = (const float*)d_in[2];
  const float* sos     = (const float*)d_in[3];
  const float* emb     = (const float*)d_in[4];
  const float* w_ih    = (const float*)d_in[5];
  const float* w_hh    = (const float*)d_in[6];
  const float* b_ih    = (const float*)d_in[7];
  const float* b_hh    = (const float*)d_in[8];
  const float* out_w   = (const float*)d_in[9];
  const float* out_b   = (const float*)d_in[10];
  float* out = (float*)d_out;

  cudaFuncSetAttribute(k_mgemm, cudaFuncAttributeMaxDynamicSharedMemorySize, SMEM_G);
  cudaFuncSetAttribute(k_eg,    cudaFuncAttributeMaxDynamicSharedMemorySize, SMEM_G);

  // per-step threefry subkeys
  uint32_t sk0[32], sk1[32];
  {
    uint32_t k0 = 0u, k1 = 1u;
    for (int t = 0; t < 32; t++) {
      uint32_t n0, n1, s0, s1;
      h_tf2x32(k0, k1, 0u, 0u, n0, n1);
      h_tf2x32(k0, k1, 0u, 1u, s0, s1);
      sk0[t] = s0; sk1[t] = s1; k0 = n0; k1 = n1;
    }
  }

  k_init<<<4096, 256>>>(b_ih, b_hh, out);                    // 1
  k_split_emb<<<4352, 256>>>(emb, sos);                      // 2
  k_split_wall<<<dim3(64, 16, 3), 256>>>(w_hh, w_ih, out_w); // 3
  k_eg<<<dim3(16, 17), 256, SMEM_G>>>();                     // 4
  k_h0<<<dim3(8, 8), 256>>>(x, agent_w, agent_b);            // 5 -> g_Ah[1]
  // bootstrap: P_0 = h0 @ Whh; gumbel step 0; (z slot 1 = garbage, unused)
  k_mgemm<<<dim3(37, 4), 256, SMEM_G>>>(1, out_b, sk0[0], sk1[0], 1, -1, out);
  k_lstm0<<<512, 256>>>();                                   // -> H_1

  for (int t = 0; t < 32; t++) {
    // z_t (slot t&1), P_{t+1}, gumbel_t; flush probs/ent of step t-1
    k_mgemm<<<dim3(37, 4), 256, SMEM_G>>>(t & 1, out_b, sk0[t], sk1[t],
                                          t & 1, t - 1, out);
    k_sample<<<512, 256>>>(out, t);                          // sym_t, LSTM(t+1)
  }
  k_ptail<<<512, 256>>>(out);                                // probs/ent t=31
}

// round 16
// speedup vs baseline: 1.9101x; 1.9101x over previous
#include <cuda_runtime.h>
#include <cuda_fp16.h>
#include <cstdint>
#include <math.h>

#define VV 2048
#define LP1 33
#define SEQ_OFF   0
#define PROBS_OFF (512*33)
#define LOGP_OFF  (PROBS_OFF + 512*33*2048)
#define ENT_OFF   (LOGP_OFF + 512*33)

// fp16 x 3-product split, K' = 3*512 = 1536.
#define KP 1536

// ---------------------------------------------------------------------------
// Persistent device scratch
// ---------------------------------------------------------------------------
__device__ __half g_Whh[2048 * KP];
__device__ __half g_Wih[2048 * KP];
__device__ __half g_Wo [2048 * KP];
__device__ __half g_E6p[2176 * KP];
__device__ __half g_Ah [2][512 * KP];
__device__ float g_EG[2176 * 2048];
__device__ float g_z [512 * 2048];
__device__ float g_P [512 * 2048];
__device__ float g_gum[512 * 2048];
__device__ float g_bg[2048];
__device__ float g_c [512 * 512];

// ---------------------------------------------------------------------------
__device__ __forceinline__ uint32_t smem_to_u32(const void* p) {
  uint32_t a;
  asm("{ .reg .u64 t; cvta.to.shared.u64 t, %1; cvt.u32.u64 %0, t; }"
      : "=r"(a) : "l"(p));
  return a;
}

__device__ __forceinline__ void split3A(float f, __half* dst, int stride) {
  __half a0 = __float2half_rn(f);
  float a0f = __half2float(a0);
  __half a1 = __float2half_rn((f - a0f) * 64.0f);
  dst[0]          = a0;
  dst[stride]     = __float2half_rn(a0f * 0.03125f);
  dst[2 * stride] = a1;
}

__device__ __forceinline__ void split3B(float f, __half* dst, int stride) {
  __half b0 = __float2half_rn(f);
  float b0f = __half2float(b0);
  __half b1 = __float2half_rn((f - b0f) * 64.0f);
  float b1f = __half2float(b1);
  dst[0]          = b0;
  dst[stride]     = __float2half_rn(b1f * 0.5f);
  dst[2 * stride] = __float2half_rn(b0f * 0.015625f);
}

// Threefry2x32 (exact JAX constants) — device
__device__ __forceinline__ void tf2x32(uint32_t k0, uint32_t k1,
                                       uint32_t x0, uint32_t x1,
                                       uint32_t& o0, uint32_t& o1) {
  uint32_t ks2 = k0 ^ k1 ^ 0x1BD11BDAu;
#define TF_ROT(x,r) (((x) << (r)) | ((x) >> (32 - (r))))
#define TF_RND(r) { x0 += x1; x1 = TF_ROT(x1, r); x1 ^= x0; }
  x0 += k0; x1 += k1;
  TF_RND(13) TF_RND(15) TF_RND(26) TF_RND(6)   x0 += k1;  x1 += ks2 + 1u;
  TF_RND(17) TF_RND(29) TF_RND(16) TF_RND(24)  x0 += ks2; x1 += k0 + 2u;
  TF_RND(13) TF_RND(15) TF_RND(26) TF_RND(6)   x0 += k0;  x1 += k1 + 3u;
  TF_RND(17) TF_RND(29) TF_RND(16) TF_RND(24)  x0 += k1;  x1 += ks2 + 4u;
  TF_RND(13) TF_RND(15) TF_RND(26) TF_RND(6)   x0 += ks2; x1 += k0 + 5u;
  o0 = x0; o1 = x1;
#undef TF_RND
#undef TF_ROT
}

static void h_tf2x32(uint32_t k0, uint32_t k1, uint32_t x0, uint32_t x1,
                     uint32_t& o0, uint32_t& o1) {
  uint32_t ks2 = k0 ^ k1 ^ 0x1BD11BDAu;
#define TF_ROT(x,r) (((x) << (r)) | ((x) >> (32 - (r))))
#define TF_RND(r) { x0 += x1; x1 = TF_ROT(x1, r); x1 ^= x0; }
  x0 += k0; x1 += k1;
  TF_RND(13) TF_RND(15) TF_RND(26) TF_RND(6)   x0 += k1;  x1 += ks2 + 1u;
  TF_RND(17) TF_RND(29) TF_RND(16) TF_RND(24)  x0 += ks2; x1 += k0 + 2u;
  TF_RND(13) TF_RND(15) TF_RND(26) TF_RND(6)   x0 += k0;  x1 += k1 + 3u;
  TF_RND(17) TF_RND(29) TF_RND(16) TF_RND(24)  x0 += k1;  x1 += ks2 + 4u;
  TF_RND(13) TF_RND(15) TF_RND(26) TF_RND(6)   x0 += ks2; x1 += k0 + 5u;
  o0 = x0; o1 = x1;
#undef TF_RND
#undef TF_ROT
}

__device__ __forceinline__ float sigf(float x) { return 1.0f / (1.0f + expf(-x)); }

__device__ __forceinline__ int perm_orig(int pn) {
  int hg = pn >> 6, gate = (pn >> 4) & 3, hl = pn & 15;
  return gate * 512 + hg * 16 + hl;
}

__device__ __forceinline__ float gumbel_of(uint32_t sk0, uint32_t sk1, uint32_t idx) {
  uint32_t o0, o1;
  tf2x32(sk0, sk1, 0u, idx, o0, o1);
  uint32_t bits = o0 ^ o1;
  float f = __uint_as_float((bits >> 9) | 0x3f800000u) - 1.0f;
  float u = fmaxf(f, 1.1754943508222875e-38f);
  return -__logf(-__logf(u));
}

__device__ __forceinline__ float lstm_one(const float* __restrict__ P,
                                          const float* __restrict__ eg,
                                          int b, int hh) {
  int hg = hh >> 4, hl = hh & 15;
  int pn = hg * 64 + hl;
  float gi = P[pn]      + eg[pn]      + g_bg[pn];
  float gf = P[pn + 16] + eg[pn + 16] + g_bg[pn + 16];
  float gg = P[pn + 32] + eg[pn + 32] + g_bg[pn + 32];
  float go = P[pn + 48] + eg[pn + 48] + g_bg[pn + 48];
  int ci = b * 512 + hh;
  float cold = g_c[ci];
  float cn = sigf(gf) * cold + sigf(gi) * tanhf(gg);
  float hn = sigf(go) * tanhf(cn);
  g_c[ci] = cn;
  return hn;
}

// ---------------------------------------------------------------------------
// Setup kernels
// ---------------------------------------------------------------------------
__global__ __launch_bounds__(256) void k_split_wall(const float* __restrict__ whh,
                                                    const float* __restrict__ wih,
                                                    const float* __restrict__ ow) {
  __shared__ float t[32][33];
  const int bx = blockIdx.x, ky = blockIdx.y, which = blockIdx.z;
  const int tx = threadIdx.x & 31, ty = threadIdx.x >> 5;
  const float* w = (which == 0) ? whh : (which == 1) ? wih : ow;
  const int col = (which == 2) ? (bx * 32 + tx) : perm_orig(bx * 32 + tx);
#pragma unroll
  for (int r = 0; r < 4; r++) {
    int kl = ty + r * 8;
    t[kl][tx] = w[(size_t)(ky * 32 + kl) * 2048 + col];
  }
  __syncthreads();
  __half* G = (which == 0) ? g_Whh : (which == 1) ? g_Wih : g_Wo;
#pragma unroll
  for (int r = 0; r < 4; r++) {
    int nl = ty + r * 8;
    int pn = bx * 32 + nl;
    int k = ky * 32 + tx;
    split3B(t[tx][nl], &G[(size_t)pn * KP + k], 512);
  }
}

__global__ __launch_bounds__(256) void k_split_emb(const float* __restrict__ emb,
                                                   const float* __restrict__ sos) {
  int idx = blockIdx.x * 256 + threadIdx.x;       // 2176*512
  int v = idx >> 9, c = idx & 511;
  float f = (v < 2048) ? emb[idx] : (v == 2048 ? sos[c] : 0.0f);
  split3A(f, &g_E6p[(size_t)v * KP + c], 512);
}

__global__ __launch_bounds__(256) void k_init(const float* __restrict__ b_ih,
                                              const float* __restrict__ b_hh,
                                              float* __restrict__ out) {
  int idx = blockIdx.x * 256 + threadIdx.x;       // 512*2048
  int b = idx >> 11, v = idx & 2047;
  out[(size_t)PROBS_OFF + ((size_t)b * LP1 + 32) * VV + v] = 1.0f;
  if (v < 512) g_c[b * 512 + v] = 0.0f;
  if (b == 0) {
    int o = perm_orig(v);
    g_bg[v] = b_ih[o] + b_hh[o];
  }
  if (v == 0) {
    out[SEQ_OFF  + b * LP1 + 32] = 0.0f;
    out[LOGP_OFF + b * LP1 + 32] = 0.0f;
    out[ENT_OFF  + b * LP1 + 32] = 0.0f;
  }
}

// ---------------------------------------------------------------------------
// SIMT fp32 GEMM for h0 (once): h0 -> g_Ah[1]
// ---------------------------------------------------------------------------
__global__ __launch_bounds__(256) void k_h0(const float* __restrict__ A,
                                            const float* __restrict__ W,
                                            const float* __restrict__ bias) {
  const int N = 512, K = 1024;
  __shared__ float As[64][17];
  __shared__ float Ws[16][64];
  const int tid = threadIdx.x;
  const int tx = tid & 15, ty = tid >> 4;
  const int m0 = blockIdx.y * 64, n0 = blockIdx.x * 64;
  float acc[4][4];
#pragma unroll
  for (int r = 0; r < 4; r++)
#pragma unroll
    for (int c = 0; c < 4; c++) acc[r][c] = 0.f;
  for (int kb = 0; kb < K; kb += 16) {
#pragma unroll
    for (int i = 0; i < 4; i++) {
      int idx = tid + i * 256;
      As[idx >> 4][idx & 15] = A[(size_t)(m0 + (idx >> 4)) * K + kb + (idx & 15)];
    }
#pragma unroll
    for (int i = 0; i < 4; i++) {
      int idx = tid + i * 256;
      Ws[idx >> 6][idx & 63] = W[(size_t)(kb + (idx >> 6)) * N + n0 + (idx & 63)];
    }
    __syncthreads();
#pragma unroll
    for (int k = 0; k < 16; k++) {
      float a[4], w[4];
#pragma unroll
      for (int r = 0; r < 4; r++) a[r] = As[ty * 4 + r][k];
#pragma unroll
      for (int c = 0; c < 4; c++) w[c] = Ws[k][tx * 4 + c];
#pragma unroll
      for (int r = 0; r < 4; r++)
#pragma unroll
        for (int c = 0; c < 4; c++) acc[r][c] = fmaf(a[r], w[c], acc[r][c]);
    }
    __syncthreads();
  }
#pragma unroll
  for (int r = 0; r < 4; r++)
#pragma unroll
    for (int c = 0; c < 4; c++) {
      int row = m0 + ty * 4 + r, col = n0 + tx * 4 + c;
      float hn = acc[r][c] + bias[col];
      split3A(hn, &g_Ah[1][(size_t)row * KP + col], 512);
    }
}

// ---------------------------------------------------------------------------
// fp16 HMMA GEMM core: 128x128 CTA tile, warp tile 64x32, BK=32, 3-stage.
// All 12 ldmatrix for a k-tile issued before the 32 MMAs (deep load MLP).
// ---------------------------------------------------------------------------
#define LDM_X4(r0,r1,r2,r3,addr) \
  asm volatile("ldmatrix.sync.aligned.m8n8.x4.shared.b16 {%0,%1,%2,%3}, [%4];" \
               : "=r"(r0), "=r"(r1), "=r"(r2), "=r"(r3) : "r"(addr))
#define MMA16816(c0,c1,c2,c3,a0,a1,a2,a3,b0,b1) \
  asm volatile("mma.sync.aligned.m16n8k16.row.col.f32.f16.f16.f32 " \
               "{%0,%1,%2,%3}, {%4,%5,%6,%7}, {%8,%9}, {%0,%1,%2,%3};" \
               : "+f"(c0), "+f"(c1), "+f"(c2), "+f"(c3) \
               : "r"(a0), "r"(a1), "r"(a2), "r"(a3), "r"(b0), "r"(b1))

#define STG_STRIDE 20480
#define SMEM_G (3 * STG_STRIDE)

__device__ __forceinline__ void gemm_core(const __half* __restrict__ A,
                                          const __half* __restrict__ Bt,
                                          int m0, int n0, float acc[4][4][4]) {
  constexpr int KT = KP / 32;      // 48
  extern __shared__ __half sm[];
  const uint32_t sbase = smem_to_u32(sm);
  const int tid = threadIdx.x;
  const int l = tid & 31, w = tid >> 5;
  const int wm = (w & 1) * 64, wn = (w >> 1) * 32;
  const int lr = tid >> 2, lc = (tid & 3) * 8;

#define LOAD_STAGE(st, kt) do {                                               \
    int kk_ = (kt) * 32;                                                      \
    uint32_t da_ = sbase + (st) * STG_STRIDE + (lr * 40 + lc) * 2;            \
    const __half* ga_ = A + (size_t)(m0 + lr) * KP + kk_ + lc;                \
    asm volatile("cp.async.cg.shared.global [%0], [%1], 16;"                  \
                 :: "r"(da_), "l"(ga_));                                      \
    asm volatile("cp.async.cg.shared.global [%0], [%1], 16;"                  \
                 :: "r"(da_ + 64 * 80), "l"(ga_ + (size_t)64 * KP));          \
    uint32_t db_ = da_ + 10240;                                               \
    const __half* gb_ = Bt + (size_t)(n0 + lr) * KP + kk_ + lc;               \
    asm volatile("cp.async.cg.shared.global [%0], [%1], 16;"                  \
                 :: "r"(db_), "l"(gb_));                                      \
    asm volatile("cp.async.cg.shared.global [%0], [%1], 16;"                  \
                 :: "r"(db_ + 64 * 80), "l"(gb_ + (size_t)64 * KP));          \
    asm volatile("cp.async.commit_group;");                                   \
  } while (0)

  LOAD_STAGE(0, 0);
  LOAD_STAGE(1, 1);

  for (int kt = 0; kt < KT; kt++) {
    if (kt + 1 < KT) asm volatile("cp.async.wait_group 1;");
    else             asm volatile("cp.async.wait_group 0;");
    __syncthreads();
    if (kt + 2 < KT) LOAD_STAGE((kt + 2) % 3, kt + 2);

    const uint32_t abase = sbase + (kt % 3) * STG_STRIDE;
    const uint32_t bbase = abase + 10240;

    uint32_t af[2][4][4];
    uint32_t bf[2][2][4];
#pragma unroll
    for (int kk2 = 0; kk2 < 2; kk2++) {
      const int kk = kk2 * 16;
#pragma unroll
      for (int fm = 0; fm < 4; fm++) {
        int row = wm + fm * 16 + (l & 15);
        int col = kk + (l >> 4) * 8;
        LDM_X4(af[kk2][fm][0], af[kk2][fm][1], af[kk2][fm][2], af[kk2][fm][3],
               abase + (row * 40 + col) * 2);
      }
#pragma unroll
      for (int f2 = 0; f2 < 2; f2++) {
        int row = wn + f2 * 16 + ((l >> 4) << 3) + (l & 7);
        int col = kk + ((l >> 3) & 1) * 8;
        LDM_X4(bf[kk2][f2][0], bf[kk2][f2][1], bf[kk2][f2][2], bf[kk2][f2][3],
               bbase + (row * 40 + col) * 2);
      }
    }
#pragma unroll
    for (int kk2 = 0; kk2 < 2; kk2++)
#pragma unroll
      for (int fm = 0; fm < 4; fm++)
#pragma unroll
        for (int fn = 0; fn < 4; fn++) {
          uint32_t b0 = bf[kk2][fn >> 1][(fn & 1) * 2];
          uint32_t b1 = bf[kk2][fn >> 1][(fn & 1) * 2 + 1];
          MMA16816(acc[fm][fn][0], acc[fm][fn][1], acc[fm][fn][2], acc[fm][fn][3],
                   af[kk2][fm][0], af[kk2][fm][1], af[kk2][fm][2], af[kk2][fm][3],
                   b0, b1);
        }
  }
#undef LOAD_STAGE
}

__device__ __forceinline__ void store_tile(float* __restrict__ out, int m0, int n0,
                                           float acc[4][4][4],
                                           const float* __restrict__ bias) {
  const int l = threadIdx.x & 31, w = threadIdx.x >> 5;
  const int wm = (w & 1) * 64, wn = (w >> 1) * 32;
#pragma unroll
  for (int fm = 0; fm < 4; fm++)
#pragma unroll
    for (int fn = 0; fn < 4; fn++) {
      int r = m0 + wm + fm * 16 + (l >> 2);
      int c = n0 + wn + fn * 8 + (l & 3) * 2;
      float b0 = bias ? bias[c] : 0.f;
      float b1 = bias ? bias[c + 1] : 0.f;
      *(float2*)&out[(size_t)r * 2048 + c] =
          make_float2(acc[fm][fn][0] + b0, acc[fm][fn][1] + b1);
      *(float2*)&out[(size_t)(r + 8) * 2048 + c] =
          make_float2(acc[fm][fn][2] + b0, acc[fm][fn][3] + b1);
    }
}

// Merged step GEMM + Gumbel CTAs: grid (37, 4) = 148 CTAs (one full wave).
// bx<16 -> z = h@Wo + ob; 16<=bx<32 -> P = h@Whh; bx>=32 -> 20 hash CTAs.
__global__ __launch_bounds__(256) void k_mgemm(int ain, const float* __restrict__ ob,
                                               uint32_t sk0, uint32_t sk1) {
  if (blockIdx.x >= 32) {
    int gid = ((blockIdx.x - 32) * 4 + blockIdx.y) * 256 + threadIdx.x;
    for (uint32_t idx = (uint32_t)gid; idx < 1048576u; idx += 5120u)
      g_gum[idx] = gumbel_of(sk0, sk1, idx);
    return;
  }
  const int half = blockIdx.x >> 4;
  const int m0 = blockIdx.y * 128, n0 = (blockIdx.x & 15) * 128;
  float acc[4][4][4];
#pragma unroll
  for (int a = 0; a < 4; a++)
#pragma unroll
    for (int b = 0; b < 4; b++)
#pragma unroll
      for (int c = 0; c < 4; c++) acc[a][b][c] = 0.f;
  gemm_core(g_Ah[ain], half ? g_Whh : g_Wo, m0, n0, acc);
  if (half) store_tile(g_P, m0, n0, acc, nullptr);
  else      store_tile(g_z, m0, n0, acc, ob);
}

// EG precompute: g_EG = E6p @ Wih, grid (16, 17)
__global__ __launch_bounds__(256) void k_eg() {
  const int m0 = blockIdx.y * 128, n0 = blockIdx.x * 128;
  float acc[4][4][4];
#pragma unroll
  for (int a = 0; a < 4; a++)
#pragma unroll
    for (int b = 0; b < 4; b++)
#pragma unroll
      for (int c = 0; c < 4; c++) acc[a][b][c] = 0.f;
  gemm_core(g_E6p, g_Wih, m0, n0, acc);
  store_tile(g_EG, m0, n0, acc, nullptr);
}

// ---------------------------------------------------------------------------
// LSTM0: iteration-0 LSTM (sym = sos row 2048) -> g_Ah[0].
// ---------------------------------------------------------------------------
__global__ __launch_bounds__(256) void k_lstm0() {
  const int b = blockIdx.x, tid = threadIdx.x;
  const float* __restrict__ P = &g_P[(size_t)b * 2048];
  const float* __restrict__ eg = &g_EG[(size_t)2048 * 2048];
#pragma unroll
  for (int r = 0; r < 2; r++) {
    int hh = tid + r * 256;
    float hn = lstm_one(P, eg, b, hh);
    split3A(hn, &g_Ah[0][(size_t)b * KP + hh], 512);
  }
}

// ---------------------------------------------------------------------------
// Sampler(t): softmax/probs/entropy/argmax (single-exp), then LSTM(t+1).
// ---------------------------------------------------------------------------
__global__ __launch_bounds__(256) void k_sample(float* __restrict__ out, int t) {
  const int b = blockIdx.x;
  const int tid = threadIdx.x;
  const float* __restrict__ z   = &g_z[(size_t)b * VV];
  const float* __restrict__ gum = &g_gum[(size_t)b * VV];

  float zv[8];
#pragma unroll
  for (int j = 0; j < 8; j++) zv[j] = z[tid + j * 256];

  __shared__ float red[256];
  __shared__ float rv[256];
  __shared__ int   ri[256];
  __shared__ int   s_sym;

  float m = zv[0];
#pragma unroll
  for (int j = 1; j < 8; j++) m = fmaxf(m, zv[j]);
  red[tid] = m; __syncthreads();
  for (int s = 128; s > 0; s >>= 1) {
    if (tid < s) red[tid] = fmaxf(red[tid], red[tid + s]);
    __syncthreads();
  }
  const float M = red[0]; __syncthreads();

  float ev[8];
  float ssum = 0.f;
#pragma unroll
  for (int j = 0; j < 8; j++) { ev[j] = __expf(zv[j] - M); ssum += ev[j]; }
  red[tid] = ssum; __syncthreads();
  for (int s = 128; s > 0; s >>= 1) {
    if (tid < s) red[tid] += red[tid + s];
    __syncthreads();
  }
  const float S = red[0];
  const float lse = logf(S);
  const float inv = 1.0f / S;
  __syncthreads();

  float entp = 0.f;
  float bestv = -INFINITY;
  int   besti = VV;
  const size_t probs_row = (size_t)PROBS_OFF + ((size_t)b * LP1 + t) * VV;
#pragma unroll
  for (int j = 0; j < 8; j++) {
    int v = tid + j * 256;
    float lsm = zv[j] - M - lse;
    float pr = ev[j] * inv;
    out[probs_row + v] = pr;
    entp += pr * lsm;
    float val = gum[v] + lsm;
    if (val > bestv || (val == bestv && v < besti)) { bestv = val; besti = v; }
  }

  // merged entropy-sum + argmax reduction ladder
  red[tid] = entp; rv[tid] = bestv; ri[tid] = besti; __syncthreads();
  for (int s = 128; s > 0; s >>= 1) {
    if (tid < s) {
      red[tid] += red[tid + s];
      if (rv[tid + s] > rv[tid] ||
          (rv[tid + s] == rv[tid] && ri[tid + s] < ri[tid])) {
        rv[tid] = rv[tid + s]; ri[tid] = ri[tid + s];
      }
    }
    __syncthreads();
  }
  if (tid == 0) {
    int sym = ri[0];
    s_sym = sym;
    out[SEQ_OFF  + b * LP1 + t] = (float)sym;
    out[LOGP_OFF + b * LP1 + t] = z[sym] - M - lse;
    out[ENT_OFF  + b * LP1 + t] = -red[0];
  }
  __syncthreads();
  const int sym = s_sym;

  // LSTM(t+1): gates = P + EG[sym] + bg -> h planes for next step
  const float* __restrict__ P  = &g_P[(size_t)b * 2048];
  const float* __restrict__ eg = &g_EG[(size_t)sym * 2048];
  __half* Aout = &g_Ah[(t + 1) & 1][(size_t)b * KP];
#pragma unroll
  for (int r = 0; r < 2; r++) {
    int hh = tid + r * 256;
    float hn = lstm_one(P, eg, b, hh);
    split3A(hn, &Aout[hh], 512);
  }
}

// ---------------------------------------------------------------------------
extern "C" void kernel_launch(void* const* d_in, const int* in_sizes, int n_in,
                              void* d_out, int out_size) {
  const float* x       = (const float*)d_in[0];
  const float* agent_w = (const float*)d_in[1];
  const float* agent_b = (const float*)d_in[2];
  const float* sos     = (const float*)d_in[3];
  const float* emb     = (const float*)d_in[4];
  const float* w_ih    = (const float*)d_in[5];
  const float* w_hh    = (const float*)d_in[6];
  const float* b_ih    = (const float*)d_in[7];
  const float* b_hh    = (const float*)d_in[8];
  const float* out_w   = (const float*)d_in[9];
  const float* out_b   = (const float*)d_in[10];
  float* out = (float*)d_out;

  cudaFuncSetAttribute(k_mgemm, cudaFuncAttributeMaxDynamicSharedMemorySize, SMEM_G);
  cudaFuncSetAttribute(k_eg,    cudaFuncAttributeMaxDynamicSharedMemorySize, SMEM_G);

  // per-step threefry subkeys
  uint32_t sk0[32], sk1[32];
  {
    uint32_t k0 = 0u, k1 = 1u;
    for (int t = 0; t < 32; t++) {
      uint32_t n0, n1, s0, s1;
      h_tf2x32(k0, k1, 0u, 0u, n0, n1);
      h_tf2x32(k0, k1, 0u, 1u, s0, s1);
      sk0[t] = s0; sk1[t] = s1; k0 = n0; k1 = n1;
    }
  }

  k_init<<<4096, 256>>>(b_ih, b_hh, out);                    // 1
  k_split_emb<<<4352, 256>>>(emb, sos);                      // 2
  k_split_wall<<<dim3(64, 16, 3), 256>>>(w_hh, w_ih, out_w); // 3
  k_eg<<<dim3(16, 17), 256, SMEM_G>>>();                     // 4
  k_h0<<<dim3(8, 8), 256>>>(x, agent_w, agent_b);            // 5 -> g_Ah[1]
  k_mgemm<<<dim3(37, 4), 256, SMEM_G>>>(1, out_b, sk0[0], sk1[0]); // 6 (profiled): P_0
  k_lstm0<<<512, 256>>>();                                   // 7 -> H_1

  for (int t = 0; t < 32; t++) {
    k_mgemm<<<dim3(37, 4), 256, SMEM_G>>>(t & 1, out_b, sk0[t], sk1[t]); // z_t, P_{t+1}, gum_t
    k_sample<<<512, 256>>>(out, t);                                      // sym_t, LSTM(t+1)
  }
}

// round 17
// speedup vs baseline: 2.3593x; 1.2352x over previous
#include <cuda_runtime.h>
#include <cuda_fp16.h>
#include <cstdint>
#include <math.h>

#define VV 2048
#define LP1 33
#define SEQ_OFF   0
#define PROBS_OFF (512*33)
#define LOGP_OFF  (PROBS_OFF + 512*33*2048)
#define ENT_OFF   (LOGP_OFF + 512*33)

// fp16 x 3-product split, K' = 3*512 = 1536.
#define KP 1536

// ---------------------------------------------------------------------------
// Persistent device scratch
// ---------------------------------------------------------------------------
__device__ __half g_Whh[2048 * KP];
__device__ __half g_Wih[2048 * KP];
__device__ __half g_Wo [2048 * KP];
__device__ __half g_E6p[2176 * KP];
__device__ __half g_Ah [2][512 * KP];
__device__ float g_EG[2176 * 2048];
__device__ float g_z [512 * 2048];
__device__ float g_P [512 * 2048];
__device__ float g_gum[512 * 2048];
__device__ float g_bg[2048];
__device__ float g_c [512 * 512];
__device__ unsigned g_gq[34];           // per-step gumbel chunk counters

// ---------------------------------------------------------------------------
__device__ __forceinline__ uint32_t smem_to_u32(const void* p) {
  uint32_t a;
  asm("{ .reg .u64 t; cvta.to.shared.u64 t, %1; cvt.u32.u64 %0, t; }"
      : "=r"(a) : "l"(p));
  return a;
}

__device__ __forceinline__ void split3A(float f, __half* dst, int stride) {
  __half a0 = __float2half_rn(f);
  float a0f = __half2float(a0);
  __half a1 = __float2half_rn((f - a0f) * 64.0f);
  dst[0]          = a0;
  dst[stride]     = __float2half_rn(a0f * 0.03125f);
  dst[2 * stride] = a1;
}

__device__ __forceinline__ void split3B(float f, __half* dst, int stride) {
  __half b0 = __float2half_rn(f);
  float b0f = __half2float(b0);
  __half b1 = __float2half_rn((f - b0f) * 64.0f);
  float b1f = __half2float(b1);
  dst[0]          = b0;
  dst[stride]     = __float2half_rn(b1f * 0.5f);
  dst[2 * stride] = __float2half_rn(b0f * 0.015625f);
}

// Threefry2x32 (exact JAX constants) — device
__device__ __forceinline__ void tf2x32(uint32_t k0, uint32_t k1,
                                       uint32_t x0, uint32_t x1,
                                       uint32_t& o0, uint32_t& o1) {
  uint32_t ks2 = k0 ^ k1 ^ 0x1BD11BDAu;
#define TF_ROT(x,r) (((x) << (r)) | ((x) >> (32 - (r))))
#define TF_RND(r) { x0 += x1; x1 = TF_ROT(x1, r); x1 ^= x0; }
  x0 += k0; x1 += k1;
  TF_RND(13) TF_RND(15) TF_RND(26) TF_RND(6)   x0 += k1;  x1 += ks2 + 1u;
  TF_RND(17) TF_RND(29) TF_RND(16) TF_RND(24)  x0 += ks2; x1 += k0 + 2u;
  TF_RND(13) TF_RND(15) TF_RND(26) TF_RND(6)   x0 += k0;  x1 += k1 + 3u;
  TF_RND(17) TF_RND(29) TF_RND(16) TF_RND(24)  x0 += k1;  x1 += ks2 + 4u;
  TF_RND(13) TF_RND(15) TF_RND(26) TF_RND(6)   x0 += ks2; x1 += k0 + 5u;
  o0 = x0; o1 = x1;
#undef TF_RND
#undef TF_ROT
}

static void h_tf2x32(uint32_t k0, uint32_t k1, uint32_t x0, uint32_t x1,
                     uint32_t& o0, uint32_t& o1) {
  uint32_t ks2 = k0 ^ k1 ^ 0x1BD11BDAu;
#define TF_ROT(x,r) (((x) << (r)) | ((x) >> (32 - (r))))
#define TF_RND(r) { x0 += x1; x1 = TF_ROT(x1, r); x1 ^= x0; }
  x0 += k0; x1 += k1;
  TF_RND(13) TF_RND(15) TF_RND(26) TF_RND(6)   x0 += k1;  x1 += ks2 + 1u;
  TF_RND(17) TF_RND(29) TF_RND(16) TF_RND(24)  x0 += ks2; x1 += k0 + 2u;
  TF_RND(13) TF_RND(15) TF_RND(26) TF_RND(6)   x0 += k0;  x1 += k1 + 3u;
  TF_RND(17) TF_RND(29) TF_RND(16) TF_RND(24)  x0 += k1;  x1 += ks2 + 4u;
  TF_RND(13) TF_RND(15) TF_RND(26) TF_RND(6)   x0 += ks2; x1 += k0 + 5u;
  o0 = x0; o1 = x1;
#undef TF_RND
#undef TF_ROT
}

__device__ __forceinline__ float sigf(float x) { return 1.0f / (1.0f + expf(-x)); }

__device__ __forceinline__ int perm_orig(int pn) {
  int hg = pn >> 6, gate = (pn >> 4) & 3, hl = pn & 15;
  return gate * 512 + hg * 16 + hl;
}

__device__ __forceinline__ float gumbel_of(uint32_t sk0, uint32_t sk1, uint32_t idx) {
  uint32_t o0, o1;
  tf2x32(sk0, sk1, 0u, idx, o0, o1);
  uint32_t bits = o0 ^ o1;
  float f = __uint_as_float((bits >> 9) | 0x3f800000u) - 1.0f;
  float u = fmaxf(f, 1.1754943508222875e-38f);
  return -__logf(-__logf(u));
}

// Work-stealing Gumbel fill: 512 chunks x 2048 elems, counter g_gq[qi].
// Deterministic output (chunk content is a pure function of (sk, chunk)).
__device__ __forceinline__ void gum_steal(int qi, uint32_t sk0, uint32_t sk1) {
  __shared__ unsigned sc;
  for (;;) {
    if (threadIdx.x == 0) sc = atomicAdd(&g_gq[qi], 1u);
    __syncthreads();
    unsigned c = sc;
    __syncthreads();
    if (c >= 512u) break;
    uint32_t base = c * 2048u;
#pragma unroll
    for (int j = 0; j < 8; j++) {
      uint32_t idx = base + (uint32_t)(j * 256 + threadIdx.x);
      g_gum[idx] = gumbel_of(sk0, sk1, idx);
    }
  }
}

__device__ __forceinline__ float lstm_one(const float* __restrict__ P,
                                          const float* __restrict__ eg,
                                          int b, int hh) {
  int hg = hh >> 4, hl = hh & 15;
  int pn = hg * 64 + hl;
  float gi = P[pn]      + eg[pn]      + g_bg[pn];
  float gf = P[pn + 16] + eg[pn + 16] + g_bg[pn + 16];
  float gg = P[pn + 32] + eg[pn + 32] + g_bg[pn + 32];
  float go = P[pn + 48] + eg[pn + 48] + g_bg[pn + 48];
  int ci = b * 512 + hh;
  float cold = g_c[ci];
  float cn = sigf(gf) * cold + sigf(gi) * tanhf(gg);
  float hn = sigf(go) * tanhf(cn);
  g_c[ci] = cn;
  return hn;
}

// ---------------------------------------------------------------------------
// Setup kernels
// ---------------------------------------------------------------------------
__global__ __launch_bounds__(256) void k_split_wall(const float* __restrict__ whh,
                                                    const float* __restrict__ wih,
                                                    const float* __restrict__ ow) {
  __shared__ float t[32][33];
  const int bx = blockIdx.x, ky = blockIdx.y, which = blockIdx.z;
  const int tx = threadIdx.x & 31, ty = threadIdx.x >> 5;
  const float* w = (which == 0) ? whh : (which == 1) ? wih : ow;
  const int col = (which == 2) ? (bx * 32 + tx) : perm_orig(bx * 32 + tx);
#pragma unroll
  for (int r = 0; r < 4; r++) {
    int kl = ty + r * 8;
    t[kl][tx] = w[(size_t)(ky * 32 + kl) * 2048 + col];
  }
  __syncthreads();
  __half* G = (which == 0) ? g_Whh : (which == 1) ? g_Wih : g_Wo;
#pragma unroll
  for (int r = 0; r < 4; r++) {
    int nl = ty + r * 8;
    int pn = bx * 32 + nl;
    int k = ky * 32 + tx;
    split3B(t[tx][nl], &G[(size_t)pn * KP + k], 512);
  }
}

__global__ __launch_bounds__(256) void k_split_emb(const float* __restrict__ emb,
                                                   const float* __restrict__ sos) {
  int idx = blockIdx.x * 256 + threadIdx.x;       // 2176*512
  int v = idx >> 9, c = idx & 511;
  float f = (v < 2048) ? emb[idx] : (v == 2048 ? sos[c] : 0.0f);
  split3A(f, &g_E6p[(size_t)v * KP + c], 512);
}

__global__ __launch_bounds__(256) void k_init(const float* __restrict__ b_ih,
                                              const float* __restrict__ b_hh,
                                              float* __restrict__ out) {
  int idx = blockIdx.x * 256 + threadIdx.x;       // 512*2048
  int b = idx >> 11, v = idx & 2047;
  out[(size_t)PROBS_OFF + ((size_t)b * LP1 + 32) * VV + v] = 1.0f;
  if (v < 512) g_c[b * 512 + v] = 0.0f;
  if (b == 0) {
    int o = perm_orig(v);
    g_bg[v] = b_ih[o] + b_hh[o];
  }
  if (idx < 34) g_gq[idx] = 0u;
  if (v == 0) {
    out[SEQ_OFF  + b * LP1 + 32] = 0.0f;
    out[LOGP_OFF + b * LP1 + 32] = 0.0f;
    out[ENT_OFF  + b * LP1 + 32] = 0.0f;
  }
}

// ---------------------------------------------------------------------------
// SIMT fp32 GEMM for h0 (once): h0 -> g_Ah[1]
// ---------------------------------------------------------------------------
__global__ __launch_bounds__(256) void k_h0(const float* __restrict__ A,
                                            const float* __restrict__ W,
                                            const float* __restrict__ bias) {
  const int N = 512, K = 1024;
  __shared__ float As[64][17];
  __shared__ float Ws[16][64];
  const int tid = threadIdx.x;
  const int tx = tid & 15, ty = tid >> 4;
  const int m0 = blockIdx.y * 64, n0 = blockIdx.x * 64;
  float acc[4][4];
#pragma unroll
  for (int r = 0; r < 4; r++)
#pragma unroll
    for (int c = 0; c < 4; c++) acc[r][c] = 0.f;
  for (int kb = 0; kb < K; kb += 16) {
#pragma unroll
    for (int i = 0; i < 4; i++) {
      int idx = tid + i * 256;
      As[idx >> 4][idx & 15] = A[(size_t)(m0 + (idx >> 4)) * K + kb + (idx & 15)];
    }
#pragma unroll
    for (int i = 0; i < 4; i++) {
      int idx = tid + i * 256;
      Ws[idx >> 6][idx & 63] = W[(size_t)(kb + (idx >> 6)) * N + n0 + (idx & 63)];
    }
    __syncthreads();
#pragma unroll
    for (int k = 0; k < 16; k++) {
      float a[4], w[4];
#pragma unroll
      for (int r = 0; r < 4; r++) a[r] = As[ty * 4 + r][k];
#pragma unroll
      for (int c = 0; c < 4; c++) w[c] = Ws[k][tx * 4 + c];
#pragma unroll
      for (int r = 0; r < 4; r++)
#pragma unroll
        for (int c = 0; c < 4; c++) acc[r][c] = fmaf(a[r], w[c], acc[r][c]);
    }
    __syncthreads();
  }
#pragma unroll
  for (int r = 0; r < 4; r++)
#pragma unroll
    for (int c = 0; c < 4; c++) {
      int row = m0 + ty * 4 + r, col = n0 + tx * 4 + c;
      float hn = acc[r][c] + bias[col];
      split3A(hn, &g_Ah[1][(size_t)row * KP + col], 512);
    }
}

// ---------------------------------------------------------------------------
// fp16 HMMA GEMM core: 128x128 CTA tile, warp tile 64x32, BK=32, 3-stage.
// ---------------------------------------------------------------------------
#define LDM_X4(r0,r1,r2,r3,addr) \
  asm volatile("ldmatrix.sync.aligned.m8n8.x4.shared.b16 {%0,%1,%2,%3}, [%4];" \
               : "=r"(r0), "=r"(r1), "=r"(r2), "=r"(r3) : "r"(addr))
#define MMA16816(c0,c1,c2,c3,a0,a1,a2,a3,b0,b1) \
  asm volatile("mma.sync.aligned.m16n8k16.row.col.f32.f16.f16.f32 " \
               "{%0,%1,%2,%3}, {%4,%5,%6,%7}, {%8,%9}, {%0,%1,%2,%3};" \
               : "+f"(c0), "+f"(c1), "+f"(c2), "+f"(c3) \
               : "r"(a0), "r"(a1), "r"(a2), "r"(a3), "r"(b0), "r"(b1))

#define STG_STRIDE 20480
#define SMEM_G (3 * STG_STRIDE)

__device__ __forceinline__ void gemm_core(const __half* __restrict__ A,
                                          const __half* __restrict__ Bt,
                                          int m0, int n0, float acc[4][4][4]) {
  constexpr int KT = KP / 32;      // 48
  extern __shared__ __half sm[];
  const uint32_t sbase = smem_to_u32(sm);
  const int tid = threadIdx.x;
  const int l = tid & 31, w = tid >> 5;
  const int wm = (w & 1) * 64, wn = (w >> 1) * 32;
  const int lr = tid >> 2, lc = (tid & 3) * 8;

#define LOAD_STAGE(st, kt) do {                                               \
    int kk_ = (kt) * 32;                                                      \
    uint32_t da_ = sbase + (st) * STG_STRIDE + (lr * 40 + lc) * 2;            \
    const __half* ga_ = A + (size_t)(m0 + lr) * KP + kk_ + lc;                \
    asm volatile("cp.async.cg.shared.global [%0], [%1], 16;"                  \
                 :: "r"(da_), "l"(ga_));                                      \
    asm volatile("cp.async.cg.shared.global [%0], [%1], 16;"                  \
                 :: "r"(da_ + 64 * 80), "l"(ga_ + (size_t)64 * KP));          \
    uint32_t db_ = da_ + 10240;                                               \
    const __half* gb_ = Bt + (size_t)(n0 + lr) * KP + kk_ + lc;               \
    asm volatile("cp.async.cg.shared.global [%0], [%1], 16;"                  \
                 :: "r"(db_), "l"(gb_));                                      \
    asm volatile("cp.async.cg.shared.global [%0], [%1], 16;"                  \
                 :: "r"(db_ + 64 * 80), "l"(gb_ + (size_t)64 * KP));          \
    asm volatile("cp.async.commit_group;");                                   \
  } while (0)

  LOAD_STAGE(0, 0);
  LOAD_STAGE(1, 1);

  for (int kt = 0; kt < KT; kt++) {
    if (kt + 1 < KT) asm volatile("cp.async.wait_group 1;");
    else             asm volatile("cp.async.wait_group 0;");
    __syncthreads();
    if (kt + 2 < KT) LOAD_STAGE((kt + 2) % 3, kt + 2);

    const uint32_t abase = sbase + (kt % 3) * STG_STRIDE;
    const uint32_t bbase = abase + 10240;

    uint32_t af[2][4][4];
    uint32_t bf[2][2][4];
#pragma unroll
    for (int kk2 = 0; kk2 < 2; kk2++) {
      const int kk = kk2 * 16;
#pragma unroll
      for (int fm = 0; fm < 4; fm++) {
        int row = wm + fm * 16 + (l & 15);
        int col = kk + (l >> 4) * 8;
        LDM_X4(af[kk2][fm][0], af[kk2][fm][1], af[kk2][fm][2], af[kk2][fm][3],
               abase + (row * 40 + col) * 2);
      }
#pragma unroll
      for (int f2 = 0; f2 < 2; f2++) {
        int row = wn + f2 * 16 + ((l >> 4) << 3) + (l & 7);
        int col = kk + ((l >> 3) & 1) * 8;
        LDM_X4(bf[kk2][f2][0], bf[kk2][f2][1], bf[kk2][f2][2], bf[kk2][f2][3],
               bbase + (row * 40 + col) * 2);
      }
    }
#pragma unroll
    for (int kk2 = 0; kk2 < 2; kk2++)
#pragma unroll
      for (int fm = 0; fm < 4; fm++)
#pragma unroll
        for (int fn = 0; fn < 4; fn++) {
          uint32_t b0 = bf[kk2][fn >> 1][(fn & 1) * 2];
          uint32_t b1 = bf[kk2][fn >> 1][(fn & 1) * 2 + 1];
          MMA16816(acc[fm][fn][0], acc[fm][fn][1], acc[fm][fn][2], acc[fm][fn][3],
                   af[kk2][fm][0], af[kk2][fm][1], af[kk2][fm][2], af[kk2][fm][3],
                   b0, b1);
        }
  }
#undef LOAD_STAGE
}

__device__ __forceinline__ void store_tile(float* __restrict__ out, int m0, int n0,
                                           float acc[4][4][4],
                                           const float* __restrict__ bias) {
  const int l = threadIdx.x & 31, w = threadIdx.x >> 5;
  const int wm = (w & 1) * 64, wn = (w >> 1) * 32;
#pragma unroll
  for (int fm = 0; fm < 4; fm++)
#pragma unroll
    for (int fn = 0; fn < 4; fn++) {
      int r = m0 + wm + fm * 16 + (l >> 2);
      int c = n0 + wn + fn * 8 + (l & 3) * 2;
      float b0 = bias ? bias[c] : 0.f;
      float b1 = bias ? bias[c + 1] : 0.f;
      *(float2*)&out[(size_t)r * 2048 + c] =
          make_float2(acc[fm][fn][0] + b0, acc[fm][fn][1] + b1);
      *(float2*)&out[(size_t)(r + 8) * 2048 + c] =
          make_float2(acc[fm][fn][2] + b0, acc[fm][fn][3] + b1);
    }
}

// Merged step GEMM + work-stealing Gumbel: grid (37, 4) = 148 CTAs.
// bx<16 -> z = h@Wo + ob; 16<=bx<32 -> P = h@Whh; bx>=32 -> 20 hash CTAs.
// GEMM CTAs join the gumbel chunk pool after their epilogue.
__global__ __launch_bounds__(256) void k_mgemm(int ain, const float* __restrict__ ob,
                                               uint32_t sk0, uint32_t sk1, int qi) {
  if (blockIdx.x >= 32) {
    gum_steal(qi, sk0, sk1);
    return;
  }
  const int half = blockIdx.x >> 4;
  const int m0 = blockIdx.y * 128, n0 = (blockIdx.x & 15) * 128;
  float acc[4][4][4];
#pragma unroll
  for (int a = 0; a < 4; a++)
#pragma unroll
    for (int b = 0; b < 4; b++)
#pragma unroll
      for (int c = 0; c < 4; c++) acc[a][b][c] = 0.f;
  gemm_core(g_Ah[ain], half ? g_Whh : g_Wo, m0, n0, acc);
  if (half) store_tile(g_P, m0, n0, acc, nullptr);
  else      store_tile(g_z, m0, n0, acc, ob);
  gum_steal(qi, sk0, sk1);
}

// EG precompute: g_EG = E6p @ Wih, grid (16, 17)
__global__ __launch_bounds__(256) void k_eg() {
  const int m0 = blockIdx.y * 128, n0 = blockIdx.x * 128;
  float acc[4][4][4];
#pragma unroll
  for (int a = 0; a < 4; a++)
#pragma unroll
    for (int b = 0; b < 4; b++)
#pragma unroll
      for (int c = 0; c < 4; c++) acc[a][b][c] = 0.f;
  gemm_core(g_E6p, g_Wih, m0, n0, acc);
  store_tile(g_EG, m0, n0, acc, nullptr);
}

// ---------------------------------------------------------------------------
// LSTM0: iteration-0 LSTM (sym = sos row 2048) -> g_Ah[0].
// ---------------------------------------------------------------------------
__global__ __launch_bounds__(256) void k_lstm0() {
  const int b = blockIdx.x, tid = threadIdx.x;
  const float* __restrict__ P = &g_P[(size_t)b * 2048];
  const float* __restrict__ eg = &g_EG[(size_t)2048 * 2048];
#pragma unroll
  for (int r = 0; r < 2; r++) {
    int hh = tid + r * 256;
    float hn = lstm_one(P, eg, b, hh);
    split3A(hn, &g_Ah[0][(size_t)b * KP + hh], 512);
  }
}

// ---------------------------------------------------------------------------
// Sampler(t): softmax/probs/entropy/argmax (single-exp), then LSTM(t+1).
// ---------------------------------------------------------------------------
__global__ __launch_bounds__(256) void k_sample(float* __restrict__ out, int t) {
  const int b = blockIdx.x;
  const int tid = threadIdx.x;
  const float* __restrict__ z   = &g_z[(size_t)b * VV];
  const float* __restrict__ gum = &g_gum[(size_t)b * VV];

  float zv[8];
#pragma unroll
  for (int j = 0; j < 8; j++) zv[j] = z[tid + j * 256];

  __shared__ float red[256];
  __shared__ float rv[256];
  __shared__ int   ri[256];
  __shared__ int   s_sym;

  float m = zv[0];
#pragma unroll
  for (int j = 1; j < 8; j++) m = fmaxf(m, zv[j]);
  red[tid] = m; __syncthreads();
  for (int s = 128; s > 0; s >>= 1) {
    if (tid < s) red[tid] = fmaxf(red[tid], red[tid + s]);
    __syncthreads();
  }
  const float M = red[0]; __syncthreads();

  float ev[8];
  float ssum = 0.f;
#pragma unroll
  for (int j = 0; j < 8; j++) { ev[j] = __expf(zv[j] - M); ssum += ev[j]; }
  red[tid] = ssum; __syncthreads();
  for (int s = 128; s > 0; s >>= 1) {
    if (tid < s) red[tid] += red[tid + s];
    __syncthreads();
  }
  const float S = red[0];
  const float lse = logf(S);
  const float inv = 1.0f / S;
  __syncthreads();

  float entp = 0.f;
  float bestv = -INFINITY;
  int   besti = VV;
  const size_t probs_row = (size_t)PROBS_OFF + ((size_t)b * LP1 + t) * VV;
#pragma unroll
  for (int j = 0; j < 8; j++) {
    int v = tid + j * 256;
    float lsm = zv[j] - M - lse;
    float pr = ev[j] * inv;
    out[probs_row + v] = pr;
    entp += pr * lsm;
    float val = gum[v] + lsm;
    if (val > bestv || (val == bestv && v < besti)) { bestv = val; besti = v; }
  }

  red[tid] = entp; rv[tid] = bestv; ri[tid] = besti; __syncthreads();
  for (int s = 128; s > 0; s >>= 1) {
    if (tid < s) {
      red[tid] += red[tid + s];
      if (rv[tid + s] > rv[tid] ||
          (rv[tid + s] == rv[tid] && ri[tid + s] < ri[tid])) {
        rv[tid] = rv[tid + s]; ri[tid] = ri[tid + s];
      }
    }
    __syncthreads();
  }
  if (tid == 0) {
    int sym = ri[0];
    s_sym = sym;
    out[SEQ_OFF  + b * LP1 + t] = (float)sym;
    out[LOGP_OFF + b * LP1 + t] = z[sym] - M - lse;
    out[ENT_OFF  + b * LP1 + t] = -red[0];
  }
  __syncthreads();
  const int sym = s_sym;

  // LSTM(t+1): gates = P + EG[sym] + bg -> h planes for next step
  const float* __restrict__ P  = &g_P[(size_t)b * 2048];
  const float* __restrict__ eg = &g_EG[(size_t)sym * 2048];
  __half* Aout = &g_Ah[(t + 1) & 1][(size_t)b * KP];
#pragma unroll
  for (int r = 0; r < 2; r++) {
    int hh = tid + r * 256;
    float hn = lstm_one(P, eg, b, hh);
    split3A(hn, &Aout[hh], 512);
  }
}

// ---------------------------------------------------------------------------
extern "C" void kernel_launch(void* const* d_in, const int* in_sizes, int n_in,
                              void* d_out, int out_size) {
  const float* x       = (const float*)d_in[0];
  const float* agent_w = (const float*)d_in[1];
  const float* agent_b = (const float*)d_in[2];
  const float* sos     = (const float*)d_in[3];
  const float* emb     = (const float*)d_in[4];
  const float* w_ih    = (const float*)d_in[5];
  const float* w_hh    = (const float*)d_in[6];
  const float* b_ih    = (const float*)d_in[7];
  const float* b_hh    = (const float*)d_in[8];
  const float* out_w   = (const float*)d_in[9];
  const float* out_b   = (const float*)d_in[10];
  float* out = (float*)d_out;

  cudaFuncSetAttribute(k_mgemm, cudaFuncAttributeMaxDynamicSharedMemorySize, SMEM_G);
  cudaFuncSetAttribute(k_eg,    cudaFuncAttributeMaxDynamicSharedMemorySize, SMEM_G);

  // per-step threefry subkeys
  uint32_t sk0[32], sk1[32];
  {
    uint32_t k0 = 0u, k1 = 1u;
    for (int t = 0; t < 32; t++) {
      uint32_t n0, n1, s0, s1;
      h_tf2x32(k0, k1, 0u, 0u, n0, n1);
      h_tf2x32(k0, k1, 0u, 1u, s0, s1);
      sk0[t] = s0; sk1[t] = s1; k0 = n0; k1 = n1;
    }
  }

  k_init<<<4096, 256>>>(b_ih, b_hh, out);                    // 1
  k_split_emb<<<4352, 256>>>(emb, sos);                      // 2
  k_split_wall<<<dim3(64, 16, 3), 256>>>(w_hh, w_ih, out_w); // 3
  k_eg<<<dim3(16, 17), 256, SMEM_G>>>();                     // 4
  k_h0<<<dim3(8, 8), 256>>>(x, agent_w, agent_b);            // 5 -> g_Ah[1]
  k_mgemm<<<dim3(37, 4), 256, SMEM_G>>>(1, out_b, sk0[0], sk1[0], 32); // 6: P_0, gum_0
  k_lstm0<<<512, 256>>>();                                   // 7 -> H_1

  for (int t = 0; t < 32; t++) {
    // z_t, P_{t+1}; gum_t re-hashed via counter slot t (bootstrap did gum_0
    // in slot 32; slot t is fresh, values identical for t=0)
    k_mgemm<<<dim3(37, 4), 256, SMEM_G>>>(t & 1, out_b, sk0[t], sk1[t], t);
    k_sample<<<512, 256>>>(out, t);
  }
}